// round 16
// baseline (speedup 1.0000x reference)
#include <cuda_runtime.h>

// Problem constants (fixed by the dataset)
#define BB   64
#define NN   2048
#define EE   32768
#define DD   256
#define HH   256

#define SE      4                  // edge-split per batch
#define EPB     (EE / SE)          // 8192 edges per split
#define SPLIT_M 16                 // gather blocks per batch
#define MPB     (NN / SPLIT_M)     // 128 rows per gather block

#define WNB     256                // k_wu grid (co-resident: >=3 blk/SM * 148)
#define CNB     128                // chain grid (1 block/SM)

// Scratch (__device__ globals, allocation-free; device-side refs only).
__device__ float g_wp[SE * BB * NN];
__device__ float g_up[SE * BB * NN];
__device__ float g_cp[SE * BB];
__device__ float g_s0[BB * DD];              // atomically accumulated S0
__device__ float g_v1[BB * HH];
__device__ float g_v2[BB * HH];

// Tree grid-barrier state (replay-safe: counters self-reset, flag toggles,
// sense read strictly pre-arrival).
__device__ int gw_leaf[16];                  // k_wu: 16 leaves x 16 blocks
__device__ int gw_root, gw_flag;
__device__ int g2_leaf[2][8];                // chain: 8 leaves x 16 blocks
__device__ int g2_root[2];
__device__ int g2_flag[2];

__device__ __forceinline__ void gbar_w() {
    __syncthreads();
    if (threadIdx.x == 0) {
        __threadfence();
        volatile int* vf = (volatile int*)&gw_flag;
        int sense = *vf;
        int leaf = blockIdx.x & 15;
        int p = atomicAdd(&gw_leaf[leaf], 1);
        if (p == 15) {
            gw_leaf[leaf] = 0;
            int q = atomicAdd(&gw_root, 1);
            if (q == 15) {
                gw_root = 0;
                __threadfence();
                atomicExch(&gw_flag, sense ^ 1);
            } else {
                while (*vf == sense) __nanosleep(32);
            }
        } else {
            while (*vf == sense) __nanosleep(32);
        }
        __threadfence();
    }
    __syncthreads();
}

__device__ __forceinline__ void gbar2(int i) {
    __syncthreads();
    if (threadIdx.x == 0) {
        __threadfence();
        volatile int* vf = (volatile int*)&g2_flag[i];
        int sense = *vf;
        int leaf = blockIdx.x & 7;
        int p = atomicAdd(&g2_leaf[i][leaf], 1);
        if (p == 15) {
            g2_leaf[i][leaf] = 0;
            int q = atomicAdd(&g2_root[i], 1);
            if (q == 7) {
                g2_root[i] = 0;
                __threadfence();
                atomicExch(&g2_flag[i], sense ^ 1);
            } else {
                while (*vf == sense) __nanosleep(32);
            }
        } else {
            while (*vf == sense) __nanosleep(32);
        }
        __threadfence();
    }
    __syncthreads();
}

// ---------------------------------------------------------------------------
// Kernel 1 (fused edge passes): grid WNB=256 (item = (b, se)), 512 threads.
//  pre:    zero g_s0 slice (64 floats per block; 256*64 = BB*DD exactly)
//  pass 1: w partials (smem scatter) -> g_wp, c -> g_cp   [R12 inner loop]
//  gbar_w  (tree barrier, co-resident blocks)
//  pass 2: stage full w; smem scatter u -> g_up            [R12 inner loop]
// ---------------------------------------------------------------------------
__global__ __launch_bounds__(512) void k_wu(const int* __restrict__ adj_row,
                                            const int* __restrict__ adj_col,
                                            const float* __restrict__ adj_val,
                                            const int* __restrict__ curlen) {
    __shared__ float sw[NN];
    __shared__ float su[NN];
    __shared__ float sc;
    int bid = blockIdx.x;
    int b   = bid >> 2;
    int se  = bid & 3;
    int tid = threadIdx.x;

    if (tid < 64) g_s0[bid * 64 + tid] = 0.f;   // zero S0 accumulator

    for (int i = tid; i < NN; i += 512) sw[i] = 0.f;
    if (tid == 0) sc = 0.f;
    __syncthreads();

    int L = curlen ? __ldg(curlen) : 512;
    size_t base = (size_t)b * EE + (size_t)se * EPB;
    const int4*   r4 = (const int4*)  (adj_row + base);
    const int4*   c4 = (const int4*)  (adj_col + base);
    const float4* v4 = (const float4*)(adj_val + base);
    const int NV = EPB / 4;

    // ---- pass 1: w scatter + c reduce ----
    float cpart = 0.f;
    for (int i = tid; i < NV; i += 512) {
        int4 r = r4[i]; int4 c = c4[i]; float4 v = v4[i];
        if (r.x < L) { atomicAdd(&sw[c.x], v.x); cpart += v.x; }
        if (r.y < L) { atomicAdd(&sw[c.y], v.y); cpart += v.y; }
        if (r.z < L) { atomicAdd(&sw[c.z], v.z); cpart += v.z; }
        if (r.w < L) { atomicAdd(&sw[c.w], v.w); cpart += v.w; }
    }
    #pragma unroll
    for (int off = 16; off > 0; off >>= 1)
        cpart += __shfl_down_sync(0xFFFFFFFFu, cpart, off);
    if ((tid & 31) == 0) atomicAdd(&sc, cpart);
    __syncthreads();

    {
        float* dst = g_wp + ((size_t)se * BB + b) * NN;
        for (int i = tid; i < NN; i += 512) dst[i] = sw[i];
        if (tid == 0) g_cp[se * BB + b] = sc;
    }

    gbar_w();

    // ---- pass 2: stage full w; smem scatter u ----
    for (int i = tid; i < NN; i += 512) {
        float w = 0.f;
        #pragma unroll
        for (int s = 0; s < SE; s++)
            w += g_wp[((size_t)s * BB + b) * NN + i];
        sw[i] = w;
        su[i] = 0.f;
    }
    __syncthreads();

    for (int i = tid; i < NV; i += 512) {
        int4 r = r4[i]; int4 c = c4[i]; float4 v = v4[i];
        atomicAdd(&su[c.x], v.x * sw[r.x]);
        atomicAdd(&su[c.y], v.y * sw[r.y]);
        atomicAdd(&su[c.z], v.z * sw[r.z]);
        atomicAdd(&su[c.w], v.w * sw[r.w]);
    }
    __syncthreads();

    {
        float* dst = g_up + ((size_t)se * BB + b) * NN;
        for (int i = tid; i < NN; i += 512) dst[i] = su[i];
    }
}

// ---------------------------------------------------------------------------
// Kernel 2: S0 gather. grid (BB, SPLIT_M)=1024, 512 threads.
// Same inner loop as R12; output via spread atomicAdd into g_s0 (262k lanes
// chip-wide, negligible) instead of per-split partial buffers.
// ---------------------------------------------------------------------------
__global__ __launch_bounds__(512) void k_s0(const int* __restrict__ neighbors,
                                            const float* __restrict__ emb) {
    __shared__ float  su[MPB];
    __shared__ int    snb[MPB];
    __shared__ float4 red[8][64];
    int b   = blockIdx.x;
    int tid = threadIdx.x;
    int m0  = blockIdx.y * MPB;

    if (tid < MPB) {
        float u = 0.f;
        #pragma unroll
        for (int s = 0; s < SE; s++)
            u += g_up[((size_t)s * BB + b) * NN + m0 + tid];
        su[tid]  = u;
        snb[tid] = neighbors[(size_t)b * NN + m0 + tid];
    }
    __syncthreads();

    int dg = tid & 63;
    int rg = tid >> 6;

    float4 acc = make_float4(0.f, 0.f, 0.f, 0.f);
    #pragma unroll
    for (int i = rg; i < MPB; i += 8) {
        float u = su[i];
        const float4* row = (const float4*)(emb + (size_t)snb[i] * DD);
        float4 e = __ldg(&row[dg]);
        acc.x += u * e.x;
        acc.y += u * e.y;
        acc.z += u * e.z;
        acc.w += u * e.w;
    }
    red[rg][dg] = acc;
    __syncthreads();

    if (tid < 64) {
        float4 s = make_float4(0.f, 0.f, 0.f, 0.f);
        #pragma unroll
        for (int r = 0; r < 8; r++) {
            float4 a = red[r][tid];
            s.x += a.x; s.y += a.y; s.z += a.z; s.w += a.w;
        }
        float* dst = g_s0 + (size_t)b * DD + tid * 4;
        atomicAdd(&dst[0], s.x);
        atomicAdd(&dst[1], s.y);
        atomicAdd(&dst[2], s.z);
        atomicAdd(&dst[3], s.w);
    }
}

// ---------------------------------------------------------------------------
// Kernel 3: persistent chain (R15; stage-1 staging reads g_s0 directly).
// grid CNB=128, 1024 threads. Block = 4 batches x 32 cols.
// ---------------------------------------------------------------------------
__global__ __launch_bounds__(1024, 1) void k_chainp(
        const float* __restrict__ W1,   const float* __restrict__ b1,
        const float* __restrict__ W2,   const float* __restrict__ b2,
        const float* __restrict__ fc1w, const float* __restrict__ fc1b,
        const int* __restrict__ curlen,
        float* __restrict__ out) {
    __shared__ float sA[4][260];
    __shared__ float sred[4][32][32];     // [bb][ks][h]
    __shared__ float scv[4];
    int bid = blockIdx.x;
    int tid = threadIdx.x;
    int bg  = bid >> 3;
    int cg  = bid & 7;
    int b0  = bg * 4;
    int h   = tid & 31;
    int ks  = tid >> 5;
    int col = cg * 32 + h;
    int L = curlen ? __ldg(curlen) : 512;
    float invL = 1.f / (float)L;

    // ---- stage 1 A: direct S0 load; c partials ----
    {
        int bb = tid >> 8;
        int hh = tid & 255;
        sA[bb][hh] = g_s0[(size_t)(b0 + bb) * DD + hh];
        if (tid < 4) {
            float c = 0.f;
            #pragma unroll
            for (int s = 0; s < SE; s++) c += g_cp[s * BB + b0 + tid];
            scv[tid] = c;
        }
    }
    __syncthreads();

    // ---- stage 1: v1 = S0 @ W1 + c*b1 ----
    {
        float a0 = 0.f, a1 = 0.f, a2 = 0.f, a3 = 0.f;
        #pragma unroll
        for (int j = 0; j < 8; j++) {
            int k = ks * 8 + j;
            float w = __ldg(&W1[(size_t)k * HH + col]);
            a0 += sA[0][k] * w; a1 += sA[1][k] * w;
            a2 += sA[2][k] * w; a3 += sA[3][k] * w;
        }
        sred[0][ks][h] = a0; sred[1][ks][h] = a1;
        sred[2][ks][h] = a2; sred[3][ks][h] = a3;
        __syncthreads();
        if (tid < 128) {
            int bb = tid >> 5, hh = tid & 31;
            float s = 0.f;
            #pragma unroll
            for (int k2 = 0; k2 < 32; k2++) s += sred[bb][k2][hh];
            s += scv[bb] * __ldg(&b1[cg * 32 + hh]);
            g_v1[(size_t)(b0 + bb) * HH + cg * 32 + hh] = s;
        }
    }
    gbar2(0);

    // ---- stage 2 A ----
    {
        int bb = tid >> 8, hh = tid & 255;
        sA[bb][hh] = g_v1[(size_t)(b0 + bb) * HH + hh];
    }
    __syncthreads();

    // ---- stage 2: v2 = (v1 @ W2)*invL + b2 ----
    {
        float a0 = 0.f, a1 = 0.f, a2 = 0.f, a3 = 0.f;
        #pragma unroll
        for (int j = 0; j < 8; j++) {
            int k = ks * 8 + j;
            float w = __ldg(&W2[(size_t)k * HH + col]);
            a0 += sA[0][k] * w; a1 += sA[1][k] * w;
            a2 += sA[2][k] * w; a3 += sA[3][k] * w;
        }
        sred[0][ks][h] = a0; sred[1][ks][h] = a1;
        sred[2][ks][h] = a2; sred[3][ks][h] = a3;
        __syncthreads();
        if (tid < 128) {
            int bb = tid >> 5, hh = tid & 31;
            float s = 0.f;
            #pragma unroll
            for (int k2 = 0; k2 < 32; k2++) s += sred[bb][k2][hh];
            s = s * invL + __ldg(&b2[cg * 32 + hh]);
            g_v2[(size_t)(b0 + bb) * HH + cg * 32 + hh] = s;
        }
    }
    gbar2(1);

    // ---- stage 3 A ----
    {
        int bb = tid >> 8, hh = tid & 255;
        sA[bb][hh] = g_v2[(size_t)(b0 + bb) * HH + hh];
    }
    __syncthreads();

    // ---- stage 3: out = relu(v2 @ fc1w + fc1b) ----
    {
        float a0 = 0.f, a1 = 0.f, a2 = 0.f, a3 = 0.f;
        #pragma unroll
        for (int j = 0; j < 8; j++) {
            int k = ks * 8 + j;
            float w = __ldg(&fc1w[(size_t)k * HH + col]);
            a0 += sA[0][k] * w; a1 += sA[1][k] * w;
            a2 += sA[2][k] * w; a3 += sA[3][k] * w;
        }
        sred[0][ks][h] = a0; sred[1][ks][h] = a1;
        sred[2][ks][h] = a2; sred[3][ks][h] = a3;
        __syncthreads();
        if (tid < 128) {
            int bb = tid >> 5, hh = tid & 31;
            float s = 0.f;
            #pragma unroll
            for (int k2 = 0; k2 < 32; k2++) s += sred[bb][k2][hh];
            s += __ldg(&fc1b[cg * 32 + hh]);
            s = s > 0.f ? s : 0.f;
            out[(size_t)(b0 + bb) * HH + cg * 32 + hh] = s;
        }
    }
}

// ---------------------------------------------------------------------------
extern "C" void kernel_launch(void* const* d_in, const int* in_sizes, int n_in,
                              void* d_out, int out_size) {
    const int*   neighbors = (const int*)  d_in[0];
    const int*   adj_row   = (const int*)  d_in[1];
    const int*   adj_col   = (const int*)  d_in[2];
    const float* adj_val   = (const float*)d_in[3];
    const float* emb       = (const float*)d_in[4];
    const float* W1        = (const float*)d_in[5];
    const float* b1        = (const float*)d_in[6];
    const float* W2        = (const float*)d_in[7];
    const float* b2        = (const float*)d_in[8];
    const float* fc1w      = (const float*)d_in[9];
    const float* fc1b      = (const float*)d_in[10];
    const int*   curlen    = (n_in >= 12) ? (const int*)d_in[11] : nullptr;
    float*       out       = (float*)d_out;

    k_wu    <<<WNB, 512>>>(adj_row, adj_col, adj_val, curlen);
    k_s0    <<<dim3(BB, SPLIT_M), 512>>>(neighbors, emb);
    k_chainp<<<CNB, 1024>>>(W1, b1, W2, b2, fc1w, fc1b, curlen, out);
}